// round 1
// baseline (speedup 1.0000x reference)
#include <cuda_runtime.h>
#include <math.h>

// Problem constants
#define T_TOK 2048   // B*T tokens
#define D_EMB 1024
#define H_EXP 2048
#define N_EXP 8
#define N_PAIR (T_TOK * 2)

// GEMM tiling
#define BM 64
#define BN 64
#define BK 16

// ---------------- device scratch (static, allocation-free) ----------------
__device__ __align__(16) int   g_cnt[N_EXP];
__device__ __align__(16) int   g_tok[N_EXP * T_TOK];
__device__ __align__(16) int   g_kk [N_EXP * T_TOK];
__device__ __align__(16) float g_wt [N_EXP * T_TOK];
__device__ __align__(16) float g_act[(size_t)N_PAIR * H_EXP]; // 32 MB
__device__ __align__(16) float g_y  [(size_t)N_PAIR * D_EMB]; // 16 MB

// ---------------- helpers ----------------
__device__ __forceinline__ float gelu_tanh(float x) {
    // jax.nn.gelu(approximate=True)
    float x3 = x * x * x;
    float inner = 0.7978845608028654f * (x + 0.044715f * x3);
    return 0.5f * x * (1.0f + tanhf(inner));
}

__global__ void zero_counts_kernel() {
    if (threadIdx.x < N_EXP) g_cnt[threadIdx.x] = 0;
}

// ---------------- gating: logits -> top2 -> sigmoid weights -> expert lists ----------------
__global__ void gating_kernel(const float* __restrict__ gin,
                              const float* __restrict__ gk,
                              const float* __restrict__ scale) {
    int t = blockIdx.x;
    const float* row = gin + (size_t)t * D_EMB;

    float p[N_EXP];
#pragma unroll
    for (int e = 0; e < N_EXP; e++) p[e] = 0.0f;

    for (int i = threadIdx.x; i < D_EMB; i += blockDim.x) {
        float v = row[i];
#pragma unroll
        for (int e = 0; e < N_EXP; e++) p[e] += v * gk[i * N_EXP + e];
    }

#pragma unroll
    for (int e = 0; e < N_EXP; e++) {
#pragma unroll
        for (int off = 16; off > 0; off >>= 1)
            p[e] += __shfl_down_sync(0xffffffffu, p[e], off);
    }

    __shared__ float sm[8][N_EXP];
    int warp = threadIdx.x >> 5, lane = threadIdx.x & 31;
    if (lane == 0) {
#pragma unroll
        for (int e = 0; e < N_EXP; e++) sm[warp][e] = p[e];
    }
    __syncthreads();

    if (threadIdx.x == 0) {
        float logit[N_EXP];
        int nw = blockDim.x >> 5;
#pragma unroll
        for (int e = 0; e < N_EXP; e++) {
            float s = 0.0f;
            for (int w = 0; w < nw; w++) s += sm[w][e];
            logit[e] = s;
        }
        // top-2 (lowest index wins ties, matching lax.top_k)
        int e0 = 0;
#pragma unroll
        for (int e = 1; e < N_EXP; e++) if (logit[e] > logit[e0]) e0 = e;
        int e1 = (e0 == 0) ? 1 : 0;
#pragma unroll
        for (int e = 0; e < N_EXP; e++)
            if (e != e0 && logit[e] > logit[e1]) e1 = e;

        float w0 = (1.0f / (1.0f + expf(-logit[e0]))) * scale[e0];
        float w1 = (1.0f / (1.0f + expf(-logit[e1]))) * scale[e1];

        int s0 = atomicAdd(&g_cnt[e0], 1);
        g_tok[e0 * T_TOK + s0] = t; g_kk[e0 * T_TOK + s0] = 0; g_wt[e0 * T_TOK + s0] = w0;
        int s1 = atomicAdd(&g_cnt[e1], 1);
        g_tok[e1 * T_TOK + s1] = t; g_kk[e1 * T_TOK + s1] = 1; g_wt[e1 * T_TOK + s1] = w1;
    }
}

// ---------------- pass 1: act = gelu(X@Wg) * (X@Wu), grouped by expert ----------------
__global__ __launch_bounds__(256) void moe_up_kernel(const float* __restrict__ x,
                                                     const float* __restrict__ wg,
                                                     const float* __restrict__ wu) {
    int e = blockIdx.z;
    int cnt = g_cnt[e];
    int m0 = blockIdx.y * BM;
    if (m0 >= cnt) return;
    int n0 = blockIdx.x * BN;

    __shared__ float As[BK][BM];
    __shared__ float Bg[BK][BN];
    __shared__ float Bu[BK][BN];
    __shared__ int   srow[BM];   // pair id per tile row (-1 invalid)

    int tid = threadIdx.x;
    if (tid < BM) {
        int slot = m0 + tid;
        int pr = -1;
        if (slot < cnt)
            pr = g_tok[e * T_TOK + slot] * 2 + g_kk[e * T_TOK + slot];
        srow[tid] = pr;
    }
    __syncthreads();

    float accg[4][4];
    float accu[4][4];
#pragma unroll
    for (int i = 0; i < 4; i++)
#pragma unroll
        for (int j = 0; j < 4; j++) { accg[i][j] = 0.0f; accu[i][j] = 0.0f; }

    const float* wge = wg + (size_t)e * D_EMB * H_EXP;
    const float* wue = wu + (size_t)e * D_EMB * H_EXP;

    int tx = tid & 15, ty = tid >> 4;
    int lr = tid >> 2;               // A loader: row 0..63
    int lkq = (tid & 3) * 4;         // A loader: k quad
    int lk = tid >> 4;               // B loader: k 0..15
    int lnq = (tid & 15) * 4;        // B loader: n quad

    for (int k0 = 0; k0 < D_EMB; k0 += BK) {
        // A tile (gathered rows)
        {
            int pr = srow[lr];
            float4 v = make_float4(0.f, 0.f, 0.f, 0.f);
            if (pr >= 0)
                v = *(const float4*)(x + (size_t)(pr >> 1) * D_EMB + k0 + lkq);
            As[lkq + 0][lr] = v.x; As[lkq + 1][lr] = v.y;
            As[lkq + 2][lr] = v.z; As[lkq + 3][lr] = v.w;
        }
        // B tiles
        {
            float4 v = *(const float4*)(wge + (size_t)(k0 + lk) * H_EXP + n0 + lnq);
            *(float4*)&Bg[lk][lnq] = v;
            float4 u = *(const float4*)(wue + (size_t)(k0 + lk) * H_EXP + n0 + lnq);
            *(float4*)&Bu[lk][lnq] = u;
        }
        __syncthreads();

#pragma unroll
        for (int kk = 0; kk < BK; kk++) {
            float4 a  = *(const float4*)&As[kk][ty * 4];
            float4 bg = *(const float4*)&Bg[kk][tx * 4];
            float4 bu = *(const float4*)&Bu[kk][tx * 4];
            float av[4] = {a.x, a.y, a.z, a.w};
            float bgv[4] = {bg.x, bg.y, bg.z, bg.w};
            float buv[4] = {bu.x, bu.y, bu.z, bu.w};
#pragma unroll
            for (int i = 0; i < 4; i++)
#pragma unroll
                for (int j = 0; j < 4; j++) {
                    accg[i][j] += av[i] * bgv[j];
                    accu[i][j] += av[i] * buv[j];
                }
        }
        __syncthreads();
    }

#pragma unroll
    for (int i = 0; i < 4; i++) {
        int m = ty * 4 + i;
        int pr = srow[m];
        if (pr >= 0) {
            float4 o;
            o.x = gelu_tanh(accg[i][0]) * accu[i][0];
            o.y = gelu_tanh(accg[i][1]) * accu[i][1];
            o.z = gelu_tanh(accg[i][2]) * accu[i][2];
            o.w = gelu_tanh(accg[i][3]) * accu[i][3];
            *(float4*)&g_act[(size_t)pr * H_EXP + n0 + tx * 4] = o;
        }
    }
}

// ---------------- pass 2: y = (act @ Wd) * weight ----------------
__global__ __launch_bounds__(256) void moe_down_kernel(const float* __restrict__ wd) {
    int e = blockIdx.z;
    int cnt = g_cnt[e];
    int m0 = blockIdx.y * BM;
    if (m0 >= cnt) return;
    int n0 = blockIdx.x * BN;

    __shared__ float As[BK][BM];
    __shared__ float Bs[BK][BN];
    __shared__ int   srow[BM];
    __shared__ float swt[BM];

    int tid = threadIdx.x;
    if (tid < BM) {
        int slot = m0 + tid;
        int pr = -1; float w = 0.0f;
        if (slot < cnt) {
            pr = g_tok[e * T_TOK + slot] * 2 + g_kk[e * T_TOK + slot];
            w = g_wt[e * T_TOK + slot];
        }
        srow[tid] = pr; swt[tid] = w;
    }
    __syncthreads();

    float acc[4][4];
#pragma unroll
    for (int i = 0; i < 4; i++)
#pragma unroll
        for (int j = 0; j < 4; j++) acc[i][j] = 0.0f;

    const float* wde = wd + (size_t)e * H_EXP * D_EMB;

    int tx = tid & 15, ty = tid >> 4;
    int lr = tid >> 2;
    int lkq = (tid & 3) * 4;
    int lk = tid >> 4;
    int lnq = (tid & 15) * 4;

    for (int k0 = 0; k0 < H_EXP; k0 += BK) {
        {
            int pr = srow[lr];
            float4 v = make_float4(0.f, 0.f, 0.f, 0.f);
            if (pr >= 0)
                v = *(const float4*)(g_act + (size_t)pr * H_EXP + k0 + lkq);
            As[lkq + 0][lr] = v.x; As[lkq + 1][lr] = v.y;
            As[lkq + 2][lr] = v.z; As[lkq + 3][lr] = v.w;
        }
        {
            float4 v = *(const float4*)(wde + (size_t)(k0 + lk) * D_EMB + n0 + lnq);
            *(float4*)&Bs[lk][lnq] = v;
        }
        __syncthreads();

#pragma unroll
        for (int kk = 0; kk < BK; kk++) {
            float4 a = *(const float4*)&As[kk][ty * 4];
            float4 b = *(const float4*)&Bs[kk][tx * 4];
            float av[4] = {a.x, a.y, a.z, a.w};
            float bv[4] = {b.x, b.y, b.z, b.w};
#pragma unroll
            for (int i = 0; i < 4; i++)
#pragma unroll
                for (int j = 0; j < 4; j++)
                    acc[i][j] += av[i] * bv[j];
        }
        __syncthreads();
    }

#pragma unroll
    for (int i = 0; i < 4; i++) {
        int m = ty * 4 + i;
        int pr = srow[m];
        if (pr >= 0) {
            float w = swt[m];
            float4 o;
            o.x = acc[i][0] * w; o.y = acc[i][1] * w;
            o.z = acc[i][2] * w; o.w = acc[i][3] * w;
            *(float4*)&g_y[(size_t)pr * D_EMB + n0 + tx * 4] = o;
        }
    }
}

// ---------------- combine the two expert contributions per token ----------------
__global__ void combine_kernel(float* __restrict__ out) {
    size_t i = (size_t)blockIdx.x * blockDim.x + threadIdx.x; // element of [T_TOK, D_EMB]
    int t = (int)(i >> 10);
    int d = (int)(i & 1023);
    out[i] = g_y[(size_t)t * 2048 + d] + g_y[(size_t)t * 2048 + 1024 + d];
}

// ---------------- launch ----------------
extern "C" void kernel_launch(void* const* d_in, const int* in_sizes, int n_in,
                              void* d_out, int out_size) {
    const float* x      = (const float*)d_in[0];
    const float* gin    = (const float*)d_in[1];
    const float* gk     = (const float*)d_in[2];
    const float* scale  = (const float*)d_in[3];
    const float* wg     = (const float*)d_in[4];
    const float* wu     = (const float*)d_in[5];
    const float* wd     = (const float*)d_in[6];
    float* out          = (float*)d_out;

    zero_counts_kernel<<<1, 32>>>();
    gating_kernel<<<T_TOK, 256>>>(gin, gk, scale);

    dim3 g1(H_EXP / BN, T_TOK / BM, N_EXP);   // 32 x 32 x 8 (most blocks early-exit)
    moe_up_kernel<<<g1, 256>>>(x, wg, wu);

    dim3 g2(D_EMB / BN, T_TOK / BM, N_EXP);   // 16 x 32 x 8
    moe_down_kernel<<<g2, 256>>>(wd);

    combine_kernel<<<(T_TOK * D_EMB) / 256, 256>>>(out);
}

// round 2
// speedup vs baseline: 1.0012x; 1.0012x over previous
#include <cuda_runtime.h>
#include <math.h>

// Problem constants
#define T_TOK 2048   // B*T tokens
#define D_EMB 1024
#define H_EXP 2048
#define N_EXP 8
#define N_PAIR (T_TOK * 2)

// GEMM tiling
#define BM 64
#define BN 64
#define BK 16

// ---------------- device scratch (static, allocation-free) ----------------
__device__ __align__(16) int   g_cnt[N_EXP];
__device__ __align__(16) int   g_tok[N_EXP * T_TOK];
__device__ __align__(16) int   g_kk [N_EXP * T_TOK];
__device__ __align__(16) float g_wt [N_EXP * T_TOK];
__device__ __align__(16) float g_act[(size_t)N_PAIR * H_EXP]; // 32 MB
__device__ __align__(16) float g_y  [(size_t)N_PAIR * D_EMB]; // 16 MB

// ---------------- helpers ----------------
__device__ __forceinline__ float gelu_tanh(float x) {
    // jax.nn.gelu(approximate=True)
    float x3 = x * x * x;
    float inner = 0.7978845608028654f * (x + 0.044715f * x3);
    return 0.5f * x * (1.0f + tanhf(inner));
}

__global__ void zero_counts_kernel() {
    if (threadIdx.x < N_EXP) g_cnt[threadIdx.x] = 0;
}

// ---------------- gating: logits -> top2 -> sigmoid weights -> expert lists ----------------
__global__ void gating_kernel(const float* __restrict__ gin,
                              const float* __restrict__ gk,
                              const float* __restrict__ scale) {
    int t = blockIdx.x;
    const float* row = gin + (size_t)t * D_EMB;

    float p[N_EXP];
#pragma unroll
    for (int e = 0; e < N_EXP; e++) p[e] = 0.0f;

    for (int i = threadIdx.x; i < D_EMB; i += blockDim.x) {
        float v = row[i];
#pragma unroll
        for (int e = 0; e < N_EXP; e++) p[e] += v * gk[i * N_EXP + e];
    }

#pragma unroll
    for (int e = 0; e < N_EXP; e++) {
#pragma unroll
        for (int off = 16; off > 0; off >>= 1)
            p[e] += __shfl_down_sync(0xffffffffu, p[e], off);
    }

    __shared__ float sm[8][N_EXP];
    int warp = threadIdx.x >> 5, lane = threadIdx.x & 31;
    if (lane == 0) {
#pragma unroll
        for (int e = 0; e < N_EXP; e++) sm[warp][e] = p[e];
    }
    __syncthreads();

    if (threadIdx.x == 0) {
        float logit[N_EXP];
        int nw = blockDim.x >> 5;
#pragma unroll
        for (int e = 0; e < N_EXP; e++) {
            float s = 0.0f;
            for (int w = 0; w < nw; w++) s += sm[w][e];
            logit[e] = s;
        }
        // top-2 (lowest index wins ties, matching lax.top_k)
        int e0 = 0;
#pragma unroll
        for (int e = 1; e < N_EXP; e++) if (logit[e] > logit[e0]) e0 = e;
        int e1 = (e0 == 0) ? 1 : 0;
#pragma unroll
        for (int e = 0; e < N_EXP; e++)
            if (e != e0 && logit[e] > logit[e1]) e1 = e;

        float w0 = (1.0f / (1.0f + expf(-logit[e0]))) * scale[e0];
        float w1 = (1.0f / (1.0f + expf(-logit[e1]))) * scale[e1];

        int s0 = atomicAdd(&g_cnt[e0], 1);
        g_tok[e0 * T_TOK + s0] = t; g_kk[e0 * T_TOK + s0] = 0; g_wt[e0 * T_TOK + s0] = w0;
        int s1 = atomicAdd(&g_cnt[e1], 1);
        g_tok[e1 * T_TOK + s1] = t; g_kk[e1 * T_TOK + s1] = 1; g_wt[e1 * T_TOK + s1] = w1;
    }
}

// ---------------- pass 1: act = gelu(X@Wg) * (X@Wu), grouped by expert ----------------
__global__ __launch_bounds__(256) void moe_up_kernel(const float* __restrict__ x,
                                                     const float* __restrict__ wg,
                                                     const float* __restrict__ wu) {
    int e = blockIdx.z;
    int cnt = g_cnt[e];
    int m0 = blockIdx.y * BM;
    if (m0 >= cnt) return;
    int n0 = blockIdx.x * BN;

    __shared__ float As[BK][BM];
    __shared__ float Bg[BK][BN];
    __shared__ float Bu[BK][BN];
    __shared__ int   srow[BM];   // pair id per tile row (-1 invalid)

    int tid = threadIdx.x;
    if (tid < BM) {
        int slot = m0 + tid;
        int pr = -1;
        if (slot < cnt)
            pr = g_tok[e * T_TOK + slot] * 2 + g_kk[e * T_TOK + slot];
        srow[tid] = pr;
    }
    __syncthreads();

    float accg[4][4];
    float accu[4][4];
#pragma unroll
    for (int i = 0; i < 4; i++)
#pragma unroll
        for (int j = 0; j < 4; j++) { accg[i][j] = 0.0f; accu[i][j] = 0.0f; }

    const float* wge = wg + (size_t)e * D_EMB * H_EXP;
    const float* wue = wu + (size_t)e * D_EMB * H_EXP;

    int tx = tid & 15, ty = tid >> 4;
    int lr = tid >> 2;               // A loader: row 0..63
    int lkq = (tid & 3) * 4;         // A loader: k quad
    int lk = tid >> 4;               // B loader: k 0..15
    int lnq = (tid & 15) * 4;        // B loader: n quad

    for (int k0 = 0; k0 < D_EMB; k0 += BK) {
        // A tile (gathered rows)
        {
            int pr = srow[lr];
            float4 v = make_float4(0.f, 0.f, 0.f, 0.f);
            if (pr >= 0)
                v = *(const float4*)(x + (size_t)(pr >> 1) * D_EMB + k0 + lkq);
            As[lkq + 0][lr] = v.x; As[lkq + 1][lr] = v.y;
            As[lkq + 2][lr] = v.z; As[lkq + 3][lr] = v.w;
        }
        // B tiles
        {
            float4 v = *(const float4*)(wge + (size_t)(k0 + lk) * H_EXP + n0 + lnq);
            *(float4*)&Bg[lk][lnq] = v;
            float4 u = *(const float4*)(wue + (size_t)(k0 + lk) * H_EXP + n0 + lnq);
            *(float4*)&Bu[lk][lnq] = u;
        }
        __syncthreads();

#pragma unroll
        for (int kk = 0; kk < BK; kk++) {
            float4 a  = *(const float4*)&As[kk][ty * 4];
            float4 bg = *(const float4*)&Bg[kk][tx * 4];
            float4 bu = *(const float4*)&Bu[kk][tx * 4];
            float av[4] = {a.x, a.y, a.z, a.w};
            float bgv[4] = {bg.x, bg.y, bg.z, bg.w};
            float buv[4] = {bu.x, bu.y, bu.z, bu.w};
#pragma unroll
            for (int i = 0; i < 4; i++)
#pragma unroll
                for (int j = 0; j < 4; j++) {
                    accg[i][j] += av[i] * bgv[j];
                    accu[i][j] += av[i] * buv[j];
                }
        }
        __syncthreads();
    }

#pragma unroll
    for (int i = 0; i < 4; i++) {
        int m = ty * 4 + i;
        int pr = srow[m];
        if (pr >= 0) {
            float4 o;
            o.x = gelu_tanh(accg[i][0]) * accu[i][0];
            o.y = gelu_tanh(accg[i][1]) * accu[i][1];
            o.z = gelu_tanh(accg[i][2]) * accu[i][2];
            o.w = gelu_tanh(accg[i][3]) * accu[i][3];
            *(float4*)&g_act[(size_t)pr * H_EXP + n0 + tx * 4] = o;
        }
    }
}

// ---------------- pass 2: y = (act @ Wd) * weight ----------------
__global__ __launch_bounds__(256) void moe_down_kernel(const float* __restrict__ wd) {
    int e = blockIdx.z;
    int cnt = g_cnt[e];
    int m0 = blockIdx.y * BM;
    if (m0 >= cnt) return;
    int n0 = blockIdx.x * BN;

    __shared__ float As[BK][BM];
    __shared__ float Bs[BK][BN];
    __shared__ int   srow[BM];
    __shared__ float swt[BM];

    int tid = threadIdx.x;
    if (tid < BM) {
        int slot = m0 + tid;
        int pr = -1; float w = 0.0f;
        if (slot < cnt) {
            pr = g_tok[e * T_TOK + slot] * 2 + g_kk[e * T_TOK + slot];
            w = g_wt[e * T_TOK + slot];
        }
        srow[tid] = pr; swt[tid] = w;
    }
    __syncthreads();

    float acc[4][4];
#pragma unroll
    for (int i = 0; i < 4; i++)
#pragma unroll
        for (int j = 0; j < 4; j++) acc[i][j] = 0.0f;

    const float* wde = wd + (size_t)e * H_EXP * D_EMB;

    int tx = tid & 15, ty = tid >> 4;
    int lr = tid >> 2;
    int lkq = (tid & 3) * 4;
    int lk = tid >> 4;
    int lnq = (tid & 15) * 4;

    for (int k0 = 0; k0 < H_EXP; k0 += BK) {
        {
            int pr = srow[lr];
            float4 v = make_float4(0.f, 0.f, 0.f, 0.f);
            if (pr >= 0)
                v = *(const float4*)(g_act + (size_t)pr * H_EXP + k0 + lkq);
            As[lkq + 0][lr] = v.x; As[lkq + 1][lr] = v.y;
            As[lkq + 2][lr] = v.z; As[lkq + 3][lr] = v.w;
        }
        {
            float4 v = *(const float4*)(wde + (size_t)(k0 + lk) * D_EMB + n0 + lnq);
            *(float4*)&Bs[lk][lnq] = v;
        }
        __syncthreads();

#pragma unroll
        for (int kk = 0; kk < BK; kk++) {
            float4 a = *(const float4*)&As[kk][ty * 4];
            float4 b = *(const float4*)&Bs[kk][tx * 4];
            float av[4] = {a.x, a.y, a.z, a.w};
            float bv[4] = {b.x, b.y, b.z, b.w};
#pragma unroll
            for (int i = 0; i < 4; i++)
#pragma unroll
                for (int j = 0; j < 4; j++)
                    acc[i][j] += av[i] * bv[j];
        }
        __syncthreads();
    }

#pragma unroll
    for (int i = 0; i < 4; i++) {
        int m = ty * 4 + i;
        int pr = srow[m];
        if (pr >= 0) {
            float w = swt[m];
            float4 o;
            o.x = acc[i][0] * w; o.y = acc[i][1] * w;
            o.z = acc[i][2] * w; o.w = acc[i][3] * w;
            *(float4*)&g_y[(size_t)pr * D_EMB + n0 + tx * 4] = o;
        }
    }
}

// ---------------- combine the two expert contributions per token ----------------
__global__ void combine_kernel(float* __restrict__ out) {
    size_t i = (size_t)blockIdx.x * blockDim.x + threadIdx.x; // element of [T_TOK, D_EMB]
    int t = (int)(i >> 10);
    int d = (int)(i & 1023);
    out[i] = g_y[(size_t)t * 2048 + d] + g_y[(size_t)t * 2048 + 1024 + d];
}

// ---------------- launch ----------------
extern "C" void kernel_launch(void* const* d_in, const int* in_sizes, int n_in,
                              void* d_out, int out_size) {
    const float* x      = (const float*)d_in[0];
    const float* gin    = (const float*)d_in[1];
    const float* gk     = (const float*)d_in[2];
    const float* scale  = (const float*)d_in[3];
    const float* wg     = (const float*)d_in[4];
    const float* wu     = (const float*)d_in[5];
    const float* wd     = (const float*)d_in[6];
    float* out          = (float*)d_out;

    zero_counts_kernel<<<1, 32>>>();
    gating_kernel<<<T_TOK, 256>>>(gin, gk, scale);

    dim3 g1(H_EXP / BN, T_TOK / BM, N_EXP);   // 32 x 32 x 8 (most blocks early-exit)
    moe_up_kernel<<<g1, 256>>>(x, wg, wu);

    dim3 g2(D_EMB / BN, T_TOK / BM, N_EXP);   // 16 x 32 x 8
    moe_down_kernel<<<g2, 256>>>(wd);

    combine_kernel<<<(T_TOK * D_EMB) / 256, 256>>>(out);
}

// round 3
// speedup vs baseline: 1.0022x; 1.0010x over previous
#include <cuda_runtime.h>
#include <math.h>

// Problem constants
#define T_TOK 2048   // B*T tokens
#define D_EMB 1024
#define H_EXP 2048
#define N_EXP 8
#define N_PAIR (T_TOK * 2)

// GEMM tiling
#define BM 64
#define BN 64
#define BK 16

// ---------------- device scratch (static, allocation-free) ----------------
__device__ __align__(16) int   g_cnt[N_EXP];
__device__ __align__(16) int   g_tok[N_EXP * T_TOK];
__device__ __align__(16) int   g_kk [N_EXP * T_TOK];
__device__ __align__(16) float g_wt [N_EXP * T_TOK];
__device__ __align__(16) float g_act[(size_t)N_PAIR * H_EXP]; // 32 MB
__device__ __align__(16) float g_y  [(size_t)N_PAIR * D_EMB]; // 16 MB

// ---------------- helpers ----------------
__device__ __forceinline__ float gelu_tanh(float x) {
    // jax.nn.gelu(approximate=True)
    float x3 = x * x * x;
    float inner = 0.7978845608028654f * (x + 0.044715f * x3);
    return 0.5f * x * (1.0f + tanhf(inner));
}

__global__ void zero_counts_kernel() {
    if (threadIdx.x < N_EXP) g_cnt[threadIdx.x] = 0;
}

// ---------------- gating: logits -> top2 -> sigmoid weights -> expert lists ----------------
__global__ void gating_kernel(const float* __restrict__ gin,
                              const float* __restrict__ gk,
                              const float* __restrict__ scale) {
    int t = blockIdx.x;
    const float* row = gin + (size_t)t * D_EMB;

    float p[N_EXP];
#pragma unroll
    for (int e = 0; e < N_EXP; e++) p[e] = 0.0f;

    for (int i = threadIdx.x; i < D_EMB; i += blockDim.x) {
        float v = row[i];
#pragma unroll
        for (int e = 0; e < N_EXP; e++) p[e] += v * gk[i * N_EXP + e];
    }

#pragma unroll
    for (int e = 0; e < N_EXP; e++) {
#pragma unroll
        for (int off = 16; off > 0; off >>= 1)
            p[e] += __shfl_down_sync(0xffffffffu, p[e], off);
    }

    __shared__ float sm[8][N_EXP];
    int warp = threadIdx.x >> 5, lane = threadIdx.x & 31;
    if (lane == 0) {
#pragma unroll
        for (int e = 0; e < N_EXP; e++) sm[warp][e] = p[e];
    }
    __syncthreads();

    if (threadIdx.x == 0) {
        float logit[N_EXP];
        int nw = blockDim.x >> 5;
#pragma unroll
        for (int e = 0; e < N_EXP; e++) {
            float s = 0.0f;
            for (int w = 0; w < nw; w++) s += sm[w][e];
            logit[e] = s;
        }
        // top-2 (lowest index wins ties, matching lax.top_k)
        int e0 = 0;
#pragma unroll
        for (int e = 1; e < N_EXP; e++) if (logit[e] > logit[e0]) e0 = e;
        int e1 = (e0 == 0) ? 1 : 0;
#pragma unroll
        for (int e = 0; e < N_EXP; e++)
            if (e != e0 && logit[e] > logit[e1]) e1 = e;

        float w0 = (1.0f / (1.0f + expf(-logit[e0]))) * scale[e0];
        float w1 = (1.0f / (1.0f + expf(-logit[e1]))) * scale[e1];

        int s0 = atomicAdd(&g_cnt[e0], 1);
        g_tok[e0 * T_TOK + s0] = t; g_kk[e0 * T_TOK + s0] = 0; g_wt[e0 * T_TOK + s0] = w0;
        int s1 = atomicAdd(&g_cnt[e1], 1);
        g_tok[e1 * T_TOK + s1] = t; g_kk[e1 * T_TOK + s1] = 1; g_wt[e1 * T_TOK + s1] = w1;
    }
}

// ---------------- pass 1: act = gelu(X@Wg) * (X@Wu), grouped by expert ----------------
__global__ __launch_bounds__(256) void moe_up_kernel(const float* __restrict__ x,
                                                     const float* __restrict__ wg,
                                                     const float* __restrict__ wu) {
    int e = blockIdx.z;
    int cnt = g_cnt[e];
    int m0 = blockIdx.y * BM;
    if (m0 >= cnt) return;
    int n0 = blockIdx.x * BN;

    __shared__ float As[BK][BM];
    __shared__ float Bg[BK][BN];
    __shared__ float Bu[BK][BN];
    __shared__ int   srow[BM];   // pair id per tile row (-1 invalid)

    int tid = threadIdx.x;
    if (tid < BM) {
        int slot = m0 + tid;
        int pr = -1;
        if (slot < cnt)
            pr = g_tok[e * T_TOK + slot] * 2 + g_kk[e * T_TOK + slot];
        srow[tid] = pr;
    }
    __syncthreads();

    float accg[4][4];
    float accu[4][4];
#pragma unroll
    for (int i = 0; i < 4; i++)
#pragma unroll
        for (int j = 0; j < 4; j++) { accg[i][j] = 0.0f; accu[i][j] = 0.0f; }

    const float* wge = wg + (size_t)e * D_EMB * H_EXP;
    const float* wue = wu + (size_t)e * D_EMB * H_EXP;

    int tx = tid & 15, ty = tid >> 4;
    int lr = tid >> 2;               // A loader: row 0..63
    int lkq = (tid & 3) * 4;         // A loader: k quad
    int lk = tid >> 4;               // B loader: k 0..15
    int lnq = (tid & 15) * 4;        // B loader: n quad

    for (int k0 = 0; k0 < D_EMB; k0 += BK) {
        // A tile (gathered rows)
        {
            int pr = srow[lr];
            float4 v = make_float4(0.f, 0.f, 0.f, 0.f);
            if (pr >= 0)
                v = *(const float4*)(x + (size_t)(pr >> 1) * D_EMB + k0 + lkq);
            As[lkq + 0][lr] = v.x; As[lkq + 1][lr] = v.y;
            As[lkq + 2][lr] = v.z; As[lkq + 3][lr] = v.w;
        }
        // B tiles
        {
            float4 v = *(const float4*)(wge + (size_t)(k0 + lk) * H_EXP + n0 + lnq);
            *(float4*)&Bg[lk][lnq] = v;
            float4 u = *(const float4*)(wue + (size_t)(k0 + lk) * H_EXP + n0 + lnq);
            *(float4*)&Bu[lk][lnq] = u;
        }
        __syncthreads();

#pragma unroll
        for (int kk = 0; kk < BK; kk++) {
            float4 a  = *(const float4*)&As[kk][ty * 4];
            float4 bg = *(const float4*)&Bg[kk][tx * 4];
            float4 bu = *(const float4*)&Bu[kk][tx * 4];
            float av[4] = {a.x, a.y, a.z, a.w};
            float bgv[4] = {bg.x, bg.y, bg.z, bg.w};
            float buv[4] = {bu.x, bu.y, bu.z, bu.w};
#pragma unroll
            for (int i = 0; i < 4; i++)
#pragma unroll
                for (int j = 0; j < 4; j++) {
                    accg[i][j] += av[i] * bgv[j];
                    accu[i][j] += av[i] * buv[j];
                }
        }
        __syncthreads();
    }

#pragma unroll
    for (int i = 0; i < 4; i++) {
        int m = ty * 4 + i;
        int pr = srow[m];
        if (pr >= 0) {
            float4 o;
            o.x = gelu_tanh(accg[i][0]) * accu[i][0];
            o.y = gelu_tanh(accg[i][1]) * accu[i][1];
            o.z = gelu_tanh(accg[i][2]) * accu[i][2];
            o.w = gelu_tanh(accg[i][3]) * accu[i][3];
            *(float4*)&g_act[(size_t)pr * H_EXP + n0 + tx * 4] = o;
        }
    }
}

// ---------------- pass 2: y = (act @ Wd) * weight ----------------
__global__ __launch_bounds__(256) void moe_down_kernel(const float* __restrict__ wd) {
    int e = blockIdx.z;
    int cnt = g_cnt[e];
    int m0 = blockIdx.y * BM;
    if (m0 >= cnt) return;
    int n0 = blockIdx.x * BN;

    __shared__ float As[BK][BM];
    __shared__ float Bs[BK][BN];
    __shared__ int   srow[BM];
    __shared__ float swt[BM];

    int tid = threadIdx.x;
    if (tid < BM) {
        int slot = m0 + tid;
        int pr = -1; float w = 0.0f;
        if (slot < cnt) {
            pr = g_tok[e * T_TOK + slot] * 2 + g_kk[e * T_TOK + slot];
            w = g_wt[e * T_TOK + slot];
        }
        srow[tid] = pr; swt[tid] = w;
    }
    __syncthreads();

    float acc[4][4];
#pragma unroll
    for (int i = 0; i < 4; i++)
#pragma unroll
        for (int j = 0; j < 4; j++) acc[i][j] = 0.0f;

    const float* wde = wd + (size_t)e * H_EXP * D_EMB;

    int tx = tid & 15, ty = tid >> 4;
    int lr = tid >> 2;
    int lkq = (tid & 3) * 4;
    int lk = tid >> 4;
    int lnq = (tid & 15) * 4;

    for (int k0 = 0; k0 < H_EXP; k0 += BK) {
        {
            int pr = srow[lr];
            float4 v = make_float4(0.f, 0.f, 0.f, 0.f);
            if (pr >= 0)
                v = *(const float4*)(g_act + (size_t)pr * H_EXP + k0 + lkq);
            As[lkq + 0][lr] = v.x; As[lkq + 1][lr] = v.y;
            As[lkq + 2][lr] = v.z; As[lkq + 3][lr] = v.w;
        }
        {
            float4 v = *(const float4*)(wde + (size_t)(k0 + lk) * D_EMB + n0 + lnq);
            *(float4*)&Bs[lk][lnq] = v;
        }
        __syncthreads();

#pragma unroll
        for (int kk = 0; kk < BK; kk++) {
            float4 a = *(const float4*)&As[kk][ty * 4];
            float4 b = *(const float4*)&Bs[kk][tx * 4];
            float av[4] = {a.x, a.y, a.z, a.w};
            float bv[4] = {b.x, b.y, b.z, b.w};
#pragma unroll
            for (int i = 0; i < 4; i++)
#pragma unroll
                for (int j = 0; j < 4; j++)
                    acc[i][j] += av[i] * bv[j];
        }
        __syncthreads();
    }

#pragma unroll
    for (int i = 0; i < 4; i++) {
        int m = ty * 4 + i;
        int pr = srow[m];
        if (pr >= 0) {
            float w = swt[m];
            float4 o;
            o.x = acc[i][0] * w; o.y = acc[i][1] * w;
            o.z = acc[i][2] * w; o.w = acc[i][3] * w;
            *(float4*)&g_y[(size_t)pr * D_EMB + n0 + tx * 4] = o;
        }
    }
}

// ---------------- combine the two expert contributions per token ----------------
__global__ void combine_kernel(float* __restrict__ out) {
    size_t i = (size_t)blockIdx.x * blockDim.x + threadIdx.x; // element of [T_TOK, D_EMB]
    int t = (int)(i >> 10);
    int d = (int)(i & 1023);
    out[i] = g_y[(size_t)t * 2048 + d] + g_y[(size_t)t * 2048 + 1024 + d];
}

// ---------------- launch ----------------
extern "C" void kernel_launch(void* const* d_in, const int* in_sizes, int n_in,
                              void* d_out, int out_size) {
    const float* x      = (const float*)d_in[0];
    const float* gin    = (const float*)d_in[1];
    const float* gk     = (const float*)d_in[2];
    const float* scale  = (const float*)d_in[3];
    const float* wg     = (const float*)d_in[4];
    const float* wu     = (const float*)d_in[5];
    const float* wd     = (const float*)d_in[6];
    float* out          = (float*)d_out;

    zero_counts_kernel<<<1, 32>>>();
    gating_kernel<<<T_TOK, 256>>>(gin, gk, scale);

    dim3 g1(H_EXP / BN, T_TOK / BM, N_EXP);   // 32 x 32 x 8 (most blocks early-exit)
    moe_up_kernel<<<g1, 256>>>(x, wg, wu);

    dim3 g2(D_EMB / BN, T_TOK / BM, N_EXP);   // 16 x 32 x 8
    moe_down_kernel<<<g2, 256>>>(wd);

    combine_kernel<<<(T_TOK * D_EMB) / 256, 256>>>(out);
}

// round 5
// speedup vs baseline: 1.8909x; 1.8867x over previous
#include <cuda_runtime.h>
#include <cstdint>
#include <math.h>

#define T_TOK 2048
#define D_EMB 1024
#define H_EXP 2048
#define N_EXP 8

#define KS 32          // fp32 K per stage
#define AW 18          // smem row stride in 32-bit words (16 data + 2 pad)

// ---------------- device scratch (static, allocation-free) ----------------
__device__ __align__(16) int   g_cnt[N_EXP];
__device__ __align__(16) int   g_pair[N_EXP * T_TOK];   // pair id = t*2 + k
__device__ __align__(16) float g_wt [N_EXP * T_TOK];
__device__ __align__(16) float g_act[(size_t)T_TOK * 2 * H_EXP]; // 32 MB
__device__ __align__(16) float g_y  [(size_t)T_TOK * 2 * D_EMB]; // 16 MB

// ---------------- helpers ----------------
__device__ __forceinline__ float gelu_tanh(float x) {
    float x3 = x * x * x;
    float inner = 0.7978845608028654f * (x + 0.044715f * x3);
    return 0.5f * x * (1.0f + tanhf(inner));
}

// fp32 pair (a -> low half / k, b -> high half / k+1) -> bf16x2 hi word + residual lo word
__device__ __forceinline__ void split2(float a, float b, uint32_t& hi, uint32_t& lo) {
    uint32_t h;
    asm("cvt.rn.bf16x2.f32 %0, %1, %2;" : "=r"(h) : "f"(b), "f"(a));
    float ah = __uint_as_float(h << 16);
    float bh = __uint_as_float(h & 0xffff0000u);
    float ar = a - ah, br = b - bh;
    uint32_t l;
    asm("cvt.rn.bf16x2.f32 %0, %1, %2;" : "=r"(l) : "f"(br), "f"(ar));
    hi = h; lo = l;
}

// warp-level bf16 MMA, fp32 accum: D(16x8) += A(16x16) * B(16x8)
__device__ __forceinline__ void hmma(float* c,
                                     uint32_t a0, uint32_t a1, uint32_t a2, uint32_t a3,
                                     uint32_t b0, uint32_t b1) {
    asm volatile(
        "mma.sync.aligned.m16n8k16.row.col.f32.bf16.bf16.f32 "
        "{%0,%1,%2,%3}, {%4,%5,%6,%7}, {%8,%9}, {%0,%1,%2,%3};"
        : "+f"(c[0]), "+f"(c[1]), "+f"(c[2]), "+f"(c[3])
        : "r"(a0), "r"(a1), "r"(a2), "r"(a3), "r"(b0), "r"(b1));
}

// ---------------- small kernels ----------------
__global__ void zero_counts_kernel() {
    if (threadIdx.x < N_EXP) g_cnt[threadIdx.x] = 0;
}

__global__ void gating_kernel(const float* __restrict__ gin,
                              const float* __restrict__ gk,
                              const float* __restrict__ scale) {
    int t = blockIdx.x;
    const float* row = gin + (size_t)t * D_EMB;
    float p[N_EXP];
#pragma unroll
    for (int e = 0; e < N_EXP; e++) p[e] = 0.0f;
    for (int i = threadIdx.x; i < D_EMB; i += blockDim.x) {
        float v = row[i];
#pragma unroll
        for (int e = 0; e < N_EXP; e++) p[e] += v * gk[i * N_EXP + e];
    }
#pragma unroll
    for (int e = 0; e < N_EXP; e++) {
#pragma unroll
        for (int off = 16; off > 0; off >>= 1)
            p[e] += __shfl_down_sync(0xffffffffu, p[e], off);
    }
    __shared__ float sm[8][N_EXP];
    int warp = threadIdx.x >> 5, lane = threadIdx.x & 31;
    if (lane == 0) {
#pragma unroll
        for (int e = 0; e < N_EXP; e++) sm[warp][e] = p[e];
    }
    __syncthreads();
    if (threadIdx.x == 0) {
        float logit[N_EXP];
        int nw = blockDim.x >> 5;
#pragma unroll
        for (int e = 0; e < N_EXP; e++) {
            float s = 0.0f;
            for (int w = 0; w < nw; w++) s += sm[w][e];
            logit[e] = s;
        }
        int e0 = 0;
#pragma unroll
        for (int e = 1; e < N_EXP; e++) if (logit[e] > logit[e0]) e0 = e;
        int e1 = (e0 == 0) ? 1 : 0;
#pragma unroll
        for (int e = 0; e < N_EXP; e++)
            if (e != e0 && logit[e] > logit[e1]) e1 = e;
        float w0 = (1.0f / (1.0f + expf(-logit[e0]))) * scale[e0];
        float w1 = (1.0f / (1.0f + expf(-logit[e1]))) * scale[e1];
        int s0 = atomicAdd(&g_cnt[e0], 1);
        g_pair[e0 * T_TOK + s0] = t * 2 + 0; g_wt[e0 * T_TOK + s0] = w0;
        int s1 = atomicAdd(&g_cnt[e1], 1);
        g_pair[e1 * T_TOK + s1] = t * 2 + 1; g_wt[e1 * T_TOK + s1] = w1;
    }
}

// ---------------- pass 1: HMMA bf16x3 fused gate/up ----------------
// CTA: 256 thr (8 warps: wm=wid&3, wn=wid>>2). Tile M128 x N64, warp 32x32.
__global__ __launch_bounds__(256, 1)
void moe_up_mma(const float* __restrict__ x,
                const float* __restrict__ wg,
                const float* __restrict__ wu) {
    int e = blockIdx.z;
    int cnt = g_cnt[e];
    int m0 = blockIdx.y * 128;
    if (m0 >= cnt) return;
    int n0 = blockIdx.x * 64;

    __shared__ uint32_t sA [2][128 * AW];   // [hi/lo][row*AW + kword]
    __shared__ uint32_t sBg[2][64 * AW];
    __shared__ uint32_t sBu[2][64 * AW];
    __shared__ int srow[128];

    int tid = threadIdx.x, lane = tid & 31, wid = tid >> 5;
    int wm = wid & 3, wn = wid >> 2;

    if (tid < 128) {
        int s = m0 + tid;
        srow[tid] = (s < cnt) ? g_pair[e * T_TOK + s] : -1;
    }
    __syncthreads();

    const float* wge = wg + (size_t)e * D_EMB * H_EXP;
    const float* wue = wu + (size_t)e * D_EMB * H_EXP;

    // B loader: 256 blocks of 4k x 4n (2 matrices x 128)
    int bmat = tid >> 7, br = tid & 127, bbn = br & 15, bbk = br >> 4;
    const float* wsel = bmat ? wue : wge;
    uint32_t* dBh = bmat ? sBu[0] : sBg[0];
    uint32_t* dBl = bmat ? sBu[1] : sBg[1];

    float acc_g[2][4][4], acc_u[2][4][4];
#pragma unroll
    for (int i = 0; i < 2; i++)
#pragma unroll
        for (int j = 0; j < 4; j++)
#pragma unroll
            for (int q = 0; q < 4; q++) { acc_g[i][j][q] = 0.f; acc_u[i][j][q] = 0.f; }

    float4 pa[4], pb[4];

    // prefetch stage 0
    {
#pragma unroll
        for (int it = 0; it < 4; it++) {
            int idx = it * 256 + tid, row = idx >> 3, q = idx & 7;
            int pr = srow[row];
            pa[it] = (pr >= 0) ? __ldg((const float4*)(x + (size_t)(pr >> 1) * D_EMB + q * 4))
                               : make_float4(0.f, 0.f, 0.f, 0.f);
        }
        const float* src = wsel + (size_t)(bbk * 4) * H_EXP + n0 + bbn * 4;
        pb[0] = __ldg((const float4*)src);
        pb[1] = __ldg((const float4*)(src + H_EXP));
        pb[2] = __ldg((const float4*)(src + 2 * H_EXP));
        pb[3] = __ldg((const float4*)(src + 3 * H_EXP));
    }

#pragma unroll 1
    for (int s = 0; s < D_EMB / KS; s++) {
        __syncthreads();   // previous MMA done before overwrite (no-op at s=0)
        // ---- convert + store stage s ----
#pragma unroll
        for (int it = 0; it < 4; it++) {
            int idx = it * 256 + tid, row = idx >> 3, q = idx & 7;
            uint32_t h0, l0, h1, l1;
            split2(pa[it].x, pa[it].y, h0, l0);
            split2(pa[it].z, pa[it].w, h1, l1);
            int o = row * AW + q * 2;
            sA[0][o] = h0; sA[0][o + 1] = h1;
            sA[1][o] = l0; sA[1][o + 1] = l1;
        }
#pragma unroll
        for (int J = 0; J < 4; J++) {
            float v0 = (&pb[0].x)[J], v1 = (&pb[1].x)[J];
            float v2 = (&pb[2].x)[J], v3 = (&pb[3].x)[J];
            uint32_t h0, l0, h1, l1;
            split2(v0, v1, h0, l0);
            split2(v2, v3, h1, l1);
            int o = (bbn * 4 + J) * AW + bbk * 2;
            dBh[o] = h0; dBh[o + 1] = h1;
            dBl[o] = l0; dBl[o + 1] = l1;
        }
        __syncthreads();

        // ---- prefetch stage s+1 ----
        if (s + 1 < D_EMB / KS) {
            int k0 = (s + 1) * KS;
#pragma unroll
            for (int it = 0; it < 4; it++) {
                int idx = it * 256 + tid, row = idx >> 3, q = idx & 7;
                int pr = srow[row];
                pa[it] = (pr >= 0) ? __ldg((const float4*)(x + (size_t)(pr >> 1) * D_EMB + k0 + q * 4))
                                   : make_float4(0.f, 0.f, 0.f, 0.f);
            }
            const float* src = wsel + (size_t)(k0 + bbk * 4) * H_EXP + n0 + bbn * 4;
            pb[0] = __ldg((const float4*)src);
            pb[1] = __ldg((const float4*)(src + H_EXP));
            pb[2] = __ldg((const float4*)(src + 2 * H_EXP));
            pb[3] = __ldg((const float4*)(src + 3 * H_EXP));
        }

        // ---- MMA over stage s ----
#pragma unroll
        for (int ks = 0; ks < 2; ks++) {
            int wbase = ks * 8 + (lane & 3);
            uint32_t ah[2][4], al[2][4];
#pragma unroll
            for (int ma = 0; ma < 2; ma++) {
                int row = wm * 32 + ma * 16 + (lane >> 2);
                int o = row * AW + wbase;
                ah[ma][0] = sA[0][o];          ah[ma][1] = sA[0][o + 8 * AW];
                ah[ma][2] = sA[0][o + 4];      ah[ma][3] = sA[0][o + 8 * AW + 4];
                al[ma][0] = sA[1][o];          al[ma][1] = sA[1][o + 8 * AW];
                al[ma][2] = sA[1][o + 4];      al[ma][3] = sA[1][o + 8 * AW + 4];
            }
#pragma unroll
            for (int na = 0; na < 4; na++) {
                int n = wn * 32 + na * 8 + (lane >> 2);
                int o = n * AW + wbase;
                uint32_t bgh0 = sBg[0][o], bgh1 = sBg[0][o + 4];
                uint32_t bgl0 = sBg[1][o], bgl1 = sBg[1][o + 4];
                uint32_t buh0 = sBu[0][o], buh1 = sBu[0][o + 4];
                uint32_t bul0 = sBu[1][o], bul1 = sBu[1][o + 4];
#pragma unroll
                for (int ma = 0; ma < 2; ma++) {
                    hmma(acc_g[ma][na], ah[ma][0], ah[ma][1], ah[ma][2], ah[ma][3], bgh0, bgh1);
                    hmma(acc_g[ma][na], al[ma][0], al[ma][1], al[ma][2], al[ma][3], bgh0, bgh1);
                    hmma(acc_g[ma][na], ah[ma][0], ah[ma][1], ah[ma][2], ah[ma][3], bgl0, bgl1);
                    hmma(acc_u[ma][na], ah[ma][0], ah[ma][1], ah[ma][2], ah[ma][3], buh0, buh1);
                    hmma(acc_u[ma][na], al[ma][0], al[ma][1], al[ma][2], al[ma][3], buh0, buh1);
                    hmma(acc_u[ma][na], ah[ma][0], ah[ma][1], ah[ma][2], ah[ma][3], bul0, bul1);
                }
            }
        }
    }

    // ---- epilogue: act = gelu(gate) * up ----
#pragma unroll
    for (int ma = 0; ma < 2; ma++) {
        int row0 = wm * 32 + ma * 16 + (lane >> 2);
#pragma unroll
        for (int half = 0; half < 2; half++) {
            int row = row0 + half * 8;
            int pr = srow[row];
            if (pr < 0) continue;
            float* dst = g_act + (size_t)pr * H_EXP + n0;
#pragma unroll
            for (int na = 0; na < 4; na++) {
                float g0 = acc_g[ma][na][half * 2 + 0], g1 = acc_g[ma][na][half * 2 + 1];
                float u0 = acc_u[ma][na][half * 2 + 0], u1 = acc_u[ma][na][half * 2 + 1];
                int col = wn * 32 + na * 8 + (lane & 3) * 2;
                float2 o = make_float2(gelu_tanh(g0) * u0, gelu_tanh(g1) * u1);
                *(float2*)(dst + col) = o;
            }
        }
    }
}

// ---------------- pass 2: HMMA bf16x3 down-proj ----------------
__global__ __launch_bounds__(256, 1)
void moe_down_mma(const float* __restrict__ wd) {
    int e = blockIdx.z;
    int cnt = g_cnt[e];
    int m0 = blockIdx.y * 128;
    if (m0 >= cnt) return;
    int n0 = blockIdx.x * 64;

    __shared__ uint32_t sA[2][128 * AW];
    __shared__ uint32_t sB[2][64 * AW];
    __shared__ int   srow[128];
    __shared__ float swt[128];

    int tid = threadIdx.x, lane = tid & 31, wid = tid >> 5;
    int wm = wid & 3, wn = wid >> 2;

    if (tid < 128) {
        int s = m0 + tid;
        if (s < cnt) { srow[tid] = g_pair[e * T_TOK + s]; swt[tid] = g_wt[e * T_TOK + s]; }
        else         { srow[tid] = -1; swt[tid] = 0.f; }
    }
    __syncthreads();

    const float* wde = wd + (size_t)e * H_EXP * D_EMB;

    int bbn = tid & 15, bbk = (tid >> 4) & 7;   // valid for tid<128
    bool bload = (tid < 128);

    float acc[2][4][4];
#pragma unroll
    for (int i = 0; i < 2; i++)
#pragma unroll
        for (int j = 0; j < 4; j++)
#pragma unroll
            for (int q = 0; q < 4; q++) acc[i][j][q] = 0.f;

    float4 pa[4], pb[4];

    {
#pragma unroll
        for (int it = 0; it < 4; it++) {
            int idx = it * 256 + tid, row = idx >> 3, q = idx & 7;
            int pr = srow[row];
            pa[it] = (pr >= 0) ? __ldg((const float4*)(g_act + (size_t)pr * H_EXP + q * 4))
                               : make_float4(0.f, 0.f, 0.f, 0.f);
        }
        if (bload) {
            const float* src = wde + (size_t)(bbk * 4) * D_EMB + n0 + bbn * 4;
            pb[0] = __ldg((const float4*)src);
            pb[1] = __ldg((const float4*)(src + D_EMB));
            pb[2] = __ldg((const float4*)(src + 2 * D_EMB));
            pb[3] = __ldg((const float4*)(src + 3 * D_EMB));
        }
    }

#pragma unroll 1
    for (int s = 0; s < H_EXP / KS; s++) {
        __syncthreads();
#pragma unroll
        for (int it = 0; it < 4; it++) {
            int idx = it * 256 + tid, row = idx >> 3, q = idx & 7;
            uint32_t h0, l0, h1, l1;
            split2(pa[it].x, pa[it].y, h0, l0);
            split2(pa[it].z, pa[it].w, h1, l1);
            int o = row * AW + q * 2;
            sA[0][o] = h0; sA[0][o + 1] = h1;
            sA[1][o] = l0; sA[1][o + 1] = l1;
        }
        if (bload) {
#pragma unroll
            for (int J = 0; J < 4; J++) {
                float v0 = (&pb[0].x)[J], v1 = (&pb[1].x)[J];
                float v2 = (&pb[2].x)[J], v3 = (&pb[3].x)[J];
                uint32_t h0, l0, h1, l1;
                split2(v0, v1, h0, l0);
                split2(v2, v3, h1, l1);
                int o = (bbn * 4 + J) * AW + bbk * 2;
                sB[0][o] = h0; sB[0][o + 1] = h1;
                sB[1][o] = l0; sB[1][o + 1] = l1;
            }
        }
        __syncthreads();

        if (s + 1 < H_EXP / KS) {
            int k0 = (s + 1) * KS;
#pragma unroll
            for (int it = 0; it < 4; it++) {
                int idx = it * 256 + tid, row = idx >> 3, q = idx & 7;
                int pr = srow[row];
                pa[it] = (pr >= 0) ? __ldg((const float4*)(g_act + (size_t)pr * H_EXP + k0 + q * 4))
                                   : make_float4(0.f, 0.f, 0.f, 0.f);
            }
            if (bload) {
                const float* src = wde + (size_t)(k0 + bbk * 4) * D_EMB + n0 + bbn * 4;
                pb[0] = __ldg((const float4*)src);
                pb[1] = __ldg((const float4*)(src + D_EMB));
                pb[2] = __ldg((const float4*)(src + 2 * D_EMB));
                pb[3] = __ldg((const float4*)(src + 3 * D_EMB));
            }
        }

#pragma unroll
        for (int ks = 0; ks < 2; ks++) {
            int wbase = ks * 8 + (lane & 3);
            uint32_t ah[2][4], al[2][4];
#pragma unroll
            for (int ma = 0; ma < 2; ma++) {
                int row = wm * 32 + ma * 16 + (lane >> 2);
                int o = row * AW + wbase;
                ah[ma][0] = sA[0][o];          ah[ma][1] = sA[0][o + 8 * AW];
                ah[ma][2] = sA[0][o + 4];      ah[ma][3] = sA[0][o + 8 * AW + 4];
                al[ma][0] = sA[1][o];          al[ma][1] = sA[1][o + 8 * AW];
                al[ma][2] = sA[1][o + 4];      al[ma][3] = sA[1][o + 8 * AW + 4];
            }
#pragma unroll
            for (int na = 0; na < 4; na++) {
                int n = wn * 32 + na * 8 + (lane >> 2);
                int o = n * AW + wbase;
                uint32_t bh0 = sB[0][o], bh1 = sB[0][o + 4];
                uint32_t bl0 = sB[1][o], bl1 = sB[1][o + 4];
#pragma unroll
                for (int ma = 0; ma < 2; ma++) {
                    hmma(acc[ma][na], ah[ma][0], ah[ma][1], ah[ma][2], ah[ma][3], bh0, bh1);
                    hmma(acc[ma][na], al[ma][0], al[ma][1], al[ma][2], al[ma][3], bh0, bh1);
                    hmma(acc[ma][na], ah[ma][0], ah[ma][1], ah[ma][2], ah[ma][3], bl0, bl1);
                }
            }
        }
    }

#pragma unroll
    for (int ma = 0; ma < 2; ma++) {
        int row0 = wm * 32 + ma * 16 + (lane >> 2);
#pragma unroll
        for (int half = 0; half < 2; half++) {
            int row = row0 + half * 8;
            int pr = srow[row];
            if (pr < 0) continue;
            float w = swt[row];
            float* dst = g_y + (size_t)pr * D_EMB + n0;
#pragma unroll
            for (int na = 0; na < 4; na++) {
                float v0 = acc[ma][na][half * 2 + 0] * w;
                float v1 = acc[ma][na][half * 2 + 1] * w;
                int col = wn * 32 + na * 8 + (lane & 3) * 2;
                *(float2*)(dst + col) = make_float2(v0, v1);
            }
        }
    }
}

// ---------------- combine ----------------
__global__ void combine_kernel(float* __restrict__ out) {
    size_t i = (size_t)blockIdx.x * blockDim.x + threadIdx.x;
    int t = (int)(i >> 10);
    int d = (int)(i & 1023);
    out[i] = g_y[(size_t)t * 2048 + d] + g_y[(size_t)t * 2048 + 1024 + d];
}

// ---------------- launch ----------------
extern "C" void kernel_launch(void* const* d_in, const int* in_sizes, int n_in,
                              void* d_out, int out_size) {
    const float* x     = (const float*)d_in[0];
    const float* gin   = (const float*)d_in[1];
    const float* gk    = (const float*)d_in[2];
    const float* scale = (const float*)d_in[3];
    const float* wg    = (const float*)d_in[4];
    const float* wu    = (const float*)d_in[5];
    const float* wd    = (const float*)d_in[6];
    float* out         = (float*)d_out;

    zero_counts_kernel<<<1, 32>>>();
    gating_kernel<<<T_TOK, 256>>>(gin, gk, scale);

    dim3 g1(H_EXP / 64, T_TOK / 128, N_EXP);   // 32 x 16 x 8 (early exit on empty m-tiles)
    moe_up_mma<<<g1, 256>>>(x, wg, wu);

    dim3 g2(D_EMB / 64, T_TOK / 128, N_EXP);   // 16 x 16 x 8
    moe_down_mma<<<g2, 256>>>(wd);

    combine_kernel<<<(T_TOK * D_EMB) / 256, 256>>>(out);
}